// round 11
// baseline (speedup 1.0000x reference)
#include <cuda_runtime.h>
#include <cstdint>

// DilatedReparamBlock == single 13x13 depthwise conv + per-channel bias.
//
// R10: tf32 block-Toeplitz implicit GEMM (R9, 198us) with the issue stream
// de-bloated:
//   - ks-outer / mt-inner: B fragment loaded ONCE per ks (shared by all 7
//     m-tiles), 28 live accumulators.
//   - B repacked as uint2 -> single conflict-free LDS64 per ks.
//   - A offsets compile-time: 8ks%20 in {0,4,8,12,16} and tig<=3 never
//     straddle the 20-col window, so ky/c20 fold into immediates under
//     full unroll (runtime wrap trackers deleted).
//   - build_B fused into prep_kernel.

#define CC   256
#define HW   56
#define PAD  6
#define TROWS 69              // 68 padded rows + 1 zero row for K-padding
#define TCOLS 68
#define TILE (TROWS * TCOLS)  // 4692
#define NKS  33               // K = 264 = 33 * 8 (13*20=260 real + 4 zero)
#define NTHR 224              // 7 warps; warp w <-> output col block xb = w

__device__ uint2 g_B2[CC * NKS * 32];  // (tf32 B[8ks+tig][g], tf32 B[8ks+tig+4][g])
__device__ float g_bias[CC];

static __device__ __forceinline__ uint32_t f2tf32(float v)
{
    uint32_t u;
    asm("cvt.rna.tf32.f32 %0, %1;" : "=r"(u) : "f"(v));
    return u;
}

__global__ void prep_kernel(const float* __restrict__ lk_w,
                            const float* __restrict__ w0, const float* __restrict__ w1,
                            const float* __restrict__ w2, const float* __restrict__ w3,
                            const float* __restrict__ w4, const float* __restrict__ w5,
                            const float* __restrict__ gamma, const float* __restrict__ beta,
                            const float* __restrict__ mean,  const float* __restrict__ var)
{
    __shared__ float sweq[169];
    int c = blockIdx.x;
    int t = threadIdx.x;

    float s[7], sh[7];
#pragma unroll
    for (int i = 0; i < 7; i++) {
        float sc = gamma[i * CC + c] * rsqrtf(var[i * CC + c] + 1e-5f);
        s[i]  = sc;
        sh[i] = beta[i * CC + c] - mean[i * CC + c] * sc;
    }
    if (t == 0)
        g_bias[c] = sh[0] + sh[1] + sh[2] + sh[3] + sh[4] + sh[5] + sh[6];

    if (t < 169) {
        int ty = t / 13, tx = t % 13;
        int dy = ty - PAD, dx = tx - PAD;
        float acc = s[0] * lk_w[c * 169 + t];

        const float* ws[6]   = { w0, w1, w2, w3, w4, w5 };
        const int    KSa[6]  = { 5, 7, 7, 3, 3, 3 };
        const int    DILa[6] = { 1, 1, 2, 3, 4, 5 };
#pragma unroll
        for (int j = 0; j < 6; j++) {
            int r = DILa[j], k = KSa[j];
            if (dy % r == 0 && dx % r == 0) {
                int a  = dy / r + (k - 1) / 2;
                int b2 = dx / r + (k - 1) / 2;
                if (a >= 0 && a < k && b2 >= 0 && b2 < k)
                    acc += s[j + 1] * ws[j][c * k * k + a * k + b2];
            }
        }
        sweq[t] = acc;
    }
    __syncthreads();

    // Build packed Toeplitz B: B[k][n] = Weq[k/20][k%20 - n] (if valid tap).
    for (int e = t; e < NKS * 32; e += blockDim.x) {
        int ks  = e >> 5;
        int r   = e & 31;
        int tig = r >> 3, g = r & 7;
        uint32_t bx = 0, by = 0;
#pragma unroll
        for (int half = 0; half < 2; half++) {
            int k = 8 * ks + tig + 4 * half;
            float v = 0.f;
            if (k < 260) {
                int ky  = k / 20;
                int c20 = k - ky * 20;
                int kx  = c20 - g;
                if (kx >= 0 && kx <= 12)
                    v = sweq[ky * 13 + kx];
            }
            if (half == 0) bx = f2tf32(v); else by = f2tf32(v);
        }
        g_B2[c * (NKS * 32) + e] = make_uint2(bx, by);
    }
}

__global__ void __launch_bounds__(NTHR, 4) conv_tc(const float* __restrict__ x,
                                                   float* __restrict__ out)
{
    __shared__ uint32_t sA[2 * TILE];    // two padded 69x68 tiles, tf32 bits
    __shared__ uint2    sB[NKS * 32];    // 8448 B
    __shared__ float    sbias;

    int bid     = blockIdx.x;
    int c       = bid & (CC - 1);
    int ib0     = (bid >> 8) * 2;
    int tid     = threadIdx.x;

    const float* xim0 = x + (size_t)(ib0 * CC + c) * (HW * HW);
    const float* xim1 = xim0 + (size_t)CC * (HW * HW);

    for (int idx = tid; idx < 2 * TILE; idx += NTHR) {
        int e = idx, img = 0;
        if (e >= TILE) { img = 1; e -= TILE; }
        int r   = e / TCOLS;
        int cc2 = e - r * TCOLS;
        int iy = r - PAD, ix = cc2 - PAD;
        float v = 0.f;
        if ((unsigned)iy < (unsigned)HW && (unsigned)ix < (unsigned)HW)
            v = (img ? xim1 : xim0)[iy * HW + ix];
        sA[idx] = f2tf32(v);
    }
    for (int t = tid; t < NKS * 32; t += NTHR)
        sB[t] = g_B2[c * (NKS * 32) + t];
    if (tid == 0) sbias = g_bias[c];
    __syncthreads();

    int warp = tid >> 5;                 // xb
    int lane = tid & 31;
    int g    = lane >> 2;                // groupID 0..7
    int tig  = lane & 3;                 // thread-in-group
    int xb   = warp;

    // Per-m-tile A bases (tig folded in) and the +8-row operand delta.
    int baseA[7], d8A[7];
#pragma unroll
    for (int mt = 0; mt < 7; mt++) {
        int m    = mt * 16 + g;
        int img  = (m >= HW) ? 1 : 0;
        int y    = m - HW * img;
        int m2   = m + 8;
        int img2 = (m2 >= HW) ? 1 : 0;
        int y2   = m2 - HW * img2;
        baseA[mt] = img * TILE + y * TCOLS + xb * 8 + tig;
        d8A[mt]   = (img2 * TILE + y2 * TCOLS) - (img * TILE + y * TCOLS);
    }

    float d[7][4];
#pragma unroll
    for (int mt = 0; mt < 7; mt++)
#pragma unroll
        for (int i = 0; i < 4; i++) d[mt][i] = 0.f;

#pragma unroll
    for (int ks = 0; ks < NKS; ks++) {
        // Compile-time A offsets: kb%20 in {0,4,8,12,16}; +tig never wraps.
        const int kb   = 8 * ks;
        const int ky0  = kb / 20;
        const int c0   = kb - 20 * ky0;
        const int off0 = ky0 * TCOLS + c0;
        const int off1 = (c0 == 16) ? (ky0 + 1) * TCOLS : off0 + 4;

        uint2 bw = sB[ks * 32 + tig * 8 + g];   // one LDS64, shared by all mt

#pragma unroll
        for (int mt = 0; mt < 7; mt++) {
            int b0 = baseA[mt], d8 = d8A[mt];
            uint32_t a0 = sA[b0 + off0];
            uint32_t a1 = sA[b0 + d8 + off0];
            uint32_t a2 = sA[b0 + off1];
            uint32_t a3 = sA[b0 + d8 + off1];
            asm volatile(
                "mma.sync.aligned.m16n8k8.row.col.f32.tf32.tf32.f32 "
                "{%0,%1,%2,%3}, {%4,%5,%6,%7}, {%8,%9}, {%0,%1,%2,%3};"
                : "+f"(d[mt][0]), "+f"(d[mt][1]), "+f"(d[mt][2]), "+f"(d[mt][3])
                : "r"(a0), "r"(a1), "r"(a2), "r"(a3), "r"(bw.x), "r"(bw.y));
        }
    }

    float bb = sbias;
#pragma unroll
    for (int mt = 0; mt < 7; mt++) {
        int m    = mt * 16 + g;
        int img  = (m >= HW) ? 1 : 0;
        int y    = m - HW * img;
        int m2   = m + 8;
        int img2 = (m2 >= HW) ? 1 : 0;
        int y2   = m2 - HW * img2;
        float* o0 = out + (size_t)((ib0 + img)  * CC + c) * (HW * HW)
                        + y  * HW + xb * 8 + 2 * tig;
        float* o1 = out + (size_t)((ib0 + img2) * CC + c) * (HW * HW)
                        + y2 * HW + xb * 8 + 2 * tig;
        reinterpret_cast<float2*>(o0)[0] = make_float2(d[mt][0] + bb, d[mt][1] + bb);
        reinterpret_cast<float2*>(o1)[0] = make_float2(d[mt][2] + bb, d[mt][3] + bb);
    }
}

extern "C" void kernel_launch(void* const* d_in, const int* in_sizes, int n_in,
                              void* d_out, int out_size)
{
    const float* x    = (const float*)d_in[0];
    const float* lk_w = (const float*)d_in[1];
    const float* w0   = (const float*)d_in[2];
    const float* w1   = (const float*)d_in[3];
    const float* w2   = (const float*)d_in[4];
    const float* w3   = (const float*)d_in[5];
    const float* w4   = (const float*)d_in[6];
    const float* w5   = (const float*)d_in[7];
    const float* g    = (const float*)d_in[8];
    const float* b    = (const float*)d_in[9];
    const float* m    = (const float*)d_in[10];
    const float* v    = (const float*)d_in[11];
    float* out = (float*)d_out;

    prep_kernel<<<CC, 256>>>(lk_w, w0, w1, w2, w3, w4, w5, g, b, m, v);

    int nimg = out_size / (HW * HW * CC);   // 32
    int grid = (nimg / 2) * CC;             // 4096 CTAs
    conv_tc<<<grid, NTHR>>>(x, out);
}

// round 12
// speedup vs baseline: 1.0720x; 1.0720x over previous
#include <cuda_runtime.h>
#include <cstdint>

// DilatedReparamBlock == single 13x13 depthwise conv + per-channel bias.
//
// R11 = R10 with the register budget fixed. R10's __launch_bounds__(224,4)
// capped regs at 72 and spilled the 28 fp32 accumulators to local memory
// (ncu: DRAM 44%, 3.6TB/s, tensor 12%). Same algorithm, launch_bounds
// (224,3) -> 97-reg cap, no spills:
//   - ks-outer / mt-inner tf32 block-Toeplitz implicit GEMM
//   - B fragment: one conflict-free LDS64 per ks, shared by 7 m-tiles
//   - A offsets compile-time folded (8ks%20 never straddles the 20-window)

#define CC   256
#define HW   56
#define PAD  6
#define TROWS 69              // 68 padded rows + 1 zero row for K-padding
#define TCOLS 68
#define TILE (TROWS * TCOLS)  // 4692
#define NKS  33               // K = 264 = 33 * 8 (13*20=260 real + 4 zero)
#define NTHR 224              // 7 warps; warp w <-> output col block xb = w

__device__ uint2 g_B2[CC * NKS * 32];  // (tf32 B[8ks+tig][g], tf32 B[8ks+tig+4][g])
__device__ float g_bias[CC];

static __device__ __forceinline__ uint32_t f2tf32(float v)
{
    uint32_t u;
    asm("cvt.rna.tf32.f32 %0, %1;" : "=r"(u) : "f"(v));
    return u;
}

__global__ void prep_kernel(const float* __restrict__ lk_w,
                            const float* __restrict__ w0, const float* __restrict__ w1,
                            const float* __restrict__ w2, const float* __restrict__ w3,
                            const float* __restrict__ w4, const float* __restrict__ w5,
                            const float* __restrict__ gamma, const float* __restrict__ beta,
                            const float* __restrict__ mean,  const float* __restrict__ var)
{
    __shared__ float sweq[169];
    int c = blockIdx.x;
    int t = threadIdx.x;

    float s[7], sh[7];
#pragma unroll
    for (int i = 0; i < 7; i++) {
        float sc = gamma[i * CC + c] * rsqrtf(var[i * CC + c] + 1e-5f);
        s[i]  = sc;
        sh[i] = beta[i * CC + c] - mean[i * CC + c] * sc;
    }
    if (t == 0)
        g_bias[c] = sh[0] + sh[1] + sh[2] + sh[3] + sh[4] + sh[5] + sh[6];

    if (t < 169) {
        int ty = t / 13, tx = t % 13;
        int dy = ty - PAD, dx = tx - PAD;
        float acc = s[0] * lk_w[c * 169 + t];

        const float* ws[6]   = { w0, w1, w2, w3, w4, w5 };
        const int    KSa[6]  = { 5, 7, 7, 3, 3, 3 };
        const int    DILa[6] = { 1, 1, 2, 3, 4, 5 };
#pragma unroll
        for (int j = 0; j < 6; j++) {
            int r = DILa[j], k = KSa[j];
            if (dy % r == 0 && dx % r == 0) {
                int a  = dy / r + (k - 1) / 2;
                int b2 = dx / r + (k - 1) / 2;
                if (a >= 0 && a < k && b2 >= 0 && b2 < k)
                    acc += s[j + 1] * ws[j][c * k * k + a * k + b2];
            }
        }
        sweq[t] = acc;
    }
    __syncthreads();

    // Build packed Toeplitz B: B[k][n] = Weq[k/20][k%20 - n] (if valid tap).
    for (int e = t; e < NKS * 32; e += blockDim.x) {
        int ks  = e >> 5;
        int r   = e & 31;
        int tig = r >> 3, g = r & 7;
        uint32_t bx = 0, by = 0;
#pragma unroll
        for (int half = 0; half < 2; half++) {
            int k = 8 * ks + tig + 4 * half;
            float v = 0.f;
            if (k < 260) {
                int ky  = k / 20;
                int c20 = k - ky * 20;
                int kx  = c20 - g;
                if (kx >= 0 && kx <= 12)
                    v = sweq[ky * 13 + kx];
            }
            if (half == 0) bx = f2tf32(v); else by = f2tf32(v);
        }
        g_B2[c * (NKS * 32) + e] = make_uint2(bx, by);
    }
}

__global__ void __launch_bounds__(NTHR, 3) conv_tc(const float* __restrict__ x,
                                                   float* __restrict__ out)
{
    __shared__ uint32_t sA[2 * TILE];    // two padded 69x68 tiles, tf32 bits
    __shared__ uint2    sB[NKS * 32];    // 8448 B
    __shared__ float    sbias;

    int bid     = blockIdx.x;
    int c       = bid & (CC - 1);
    int ib0     = (bid >> 8) * 2;
    int tid     = threadIdx.x;

    const float* xim0 = x + (size_t)(ib0 * CC + c) * (HW * HW);
    const float* xim1 = xim0 + (size_t)CC * (HW * HW);

    for (int idx = tid; idx < 2 * TILE; idx += NTHR) {
        int e = idx, img = 0;
        if (e >= TILE) { img = 1; e -= TILE; }
        int r   = e / TCOLS;
        int cc2 = e - r * TCOLS;
        int iy = r - PAD, ix = cc2 - PAD;
        float v = 0.f;
        if ((unsigned)iy < (unsigned)HW && (unsigned)ix < (unsigned)HW)
            v = (img ? xim1 : xim0)[iy * HW + ix];
        sA[idx] = f2tf32(v);
    }
    for (int t = tid; t < NKS * 32; t += NTHR)
        sB[t] = g_B2[c * (NKS * 32) + t];
    if (tid == 0) sbias = g_bias[c];
    __syncthreads();

    int warp = tid >> 5;                 // xb
    int lane = tid & 31;
    int g    = lane >> 2;                // groupID 0..7
    int tig  = lane & 3;                 // thread-in-group
    int xb   = warp;

    // Per-m-tile A bases (tig folded in) and the +8-row operand delta.
    int baseA[7], d8A[7];
#pragma unroll
    for (int mt = 0; mt < 7; mt++) {
        int m    = mt * 16 + g;
        int img  = (m >= HW) ? 1 : 0;
        int y    = m - HW * img;
        int m2   = m + 8;
        int img2 = (m2 >= HW) ? 1 : 0;
        int y2   = m2 - HW * img2;
        baseA[mt] = img * TILE + y * TCOLS + xb * 8 + tig;
        d8A[mt]   = (img2 * TILE + y2 * TCOLS) - (img * TILE + y * TCOLS);
    }

    float d[7][4];
#pragma unroll
    for (int mt = 0; mt < 7; mt++)
#pragma unroll
        for (int i = 0; i < 4; i++) d[mt][i] = 0.f;

#pragma unroll
    for (int ks = 0; ks < NKS; ks++) {
        // Compile-time A offsets: kb%20 in {0,4,8,12,16}; +tig never wraps.
        const int kb   = 8 * ks;
        const int ky0  = kb / 20;
        const int c0   = kb - 20 * ky0;
        const int off0 = ky0 * TCOLS + c0;
        const int off1 = (c0 == 16) ? (ky0 + 1) * TCOLS : off0 + 4;

        uint2 bw = sB[ks * 32 + tig * 8 + g];   // one LDS64, shared by all mt

#pragma unroll
        for (int mt = 0; mt < 7; mt++) {
            int b0 = baseA[mt], d8 = d8A[mt];
            uint32_t a0 = sA[b0 + off0];
            uint32_t a1 = sA[b0 + d8 + off0];
            uint32_t a2 = sA[b0 + off1];
            uint32_t a3 = sA[b0 + d8 + off1];
            asm volatile(
                "mma.sync.aligned.m16n8k8.row.col.f32.tf32.tf32.f32 "
                "{%0,%1,%2,%3}, {%4,%5,%6,%7}, {%8,%9}, {%0,%1,%2,%3};"
                : "+f"(d[mt][0]), "+f"(d[mt][1]), "+f"(d[mt][2]), "+f"(d[mt][3])
                : "r"(a0), "r"(a1), "r"(a2), "r"(a3), "r"(bw.x), "r"(bw.y));
        }
    }

    float bb = sbias;
#pragma unroll
    for (int mt = 0; mt < 7; mt++) {
        int m    = mt * 16 + g;
        int img  = (m >= HW) ? 1 : 0;
        int y    = m - HW * img;
        int m2   = m + 8;
        int img2 = (m2 >= HW) ? 1 : 0;
        int y2   = m2 - HW * img2;
        float* o0 = out + (size_t)((ib0 + img)  * CC + c) * (HW * HW)
                        + y  * HW + xb * 8 + 2 * tig;
        float* o1 = out + (size_t)((ib0 + img2) * CC + c) * (HW * HW)
                        + y2 * HW + xb * 8 + 2 * tig;
        reinterpret_cast<float2*>(o0)[0] = make_float2(d[mt][0] + bb, d[mt][1] + bb);
        reinterpret_cast<float2*>(o1)[0] = make_float2(d[mt][2] + bb, d[mt][3] + bb);
    }
}

extern "C" void kernel_launch(void* const* d_in, const int* in_sizes, int n_in,
                              void* d_out, int out_size)
{
    const float* x    = (const float*)d_in[0];
    const float* lk_w = (const float*)d_in[1];
    const float* w0   = (const float*)d_in[2];
    const float* w1   = (const float*)d_in[3];
    const float* w2   = (const float*)d_in[4];
    const float* w3   = (const float*)d_in[5];
    const float* w4   = (const float*)d_in[6];
    const float* w5   = (const float*)d_in[7];
    const float* g    = (const float*)d_in[8];
    const float* b    = (const float*)d_in[9];
    const float* m    = (const float*)d_in[10];
    const float* v    = (const float*)d_in[11];
    float* out = (float*)d_out;

    prep_kernel<<<CC, 256>>>(lk_w, w0, w1, w2, w3, w4, w5, g, b, m, v);

    int nimg = out_size / (HW * HW * CC);   // 32
    int grid = (nimg / 2) * CC;             // 4096 CTAs
    conv_tc<<<grid, NTHR>>>(x, out);
}

// round 13
// speedup vs baseline: 1.1787x; 1.0995x over previous
#include <cuda_runtime.h>
#include <cstdint>

// DilatedReparamBlock == single 13x13 depthwise conv + per-channel bias.
//
// R12: tf32 block-Toeplitz implicit GEMM, spill-proofed. R10/R11 kept all 28
// accumulators live through a fully-unrolled 33-step K loop -> ptxas spilled
// (DRAM 40%, 3.3TB/s local traffic). Now TWO sequential ks-passes over
// disjoint m-tile groups (4 tiles then 3): peak live state ~16 accs -> no
// spills at launch_bounds(224,3). B loads double (33->66 LDS64, noise);
// A traffic unchanged; compile-time A offsets kept.

#define CC   256
#define HW   56
#define PAD  6
#define TROWS 69              // 68 padded rows + 1 zero row for K-padding
#define TCOLS 68
#define TILE (TROWS * TCOLS)  // 4692
#define NKS  33               // K = 264 = 33 * 8 (13*20=260 real + 4 zero)
#define NTHR 224              // 7 warps; warp w <-> output col block xb = w

__device__ uint2 g_B2[CC * NKS * 32];  // (tf32 B[8ks+tig][g], B[8ks+tig+4][g])
__device__ float g_bias[CC];

static __device__ __forceinline__ uint32_t f2tf32(float v)
{
    uint32_t u;
    asm("cvt.rna.tf32.f32 %0, %1;" : "=r"(u) : "f"(v));
    return u;
}

__global__ void prep_kernel(const float* __restrict__ lk_w,
                            const float* __restrict__ w0, const float* __restrict__ w1,
                            const float* __restrict__ w2, const float* __restrict__ w3,
                            const float* __restrict__ w4, const float* __restrict__ w5,
                            const float* __restrict__ gamma, const float* __restrict__ beta,
                            const float* __restrict__ mean,  const float* __restrict__ var)
{
    __shared__ float sweq[169];
    int c = blockIdx.x;
    int t = threadIdx.x;

    float s[7], sh[7];
#pragma unroll
    for (int i = 0; i < 7; i++) {
        float sc = gamma[i * CC + c] * rsqrtf(var[i * CC + c] + 1e-5f);
        s[i]  = sc;
        sh[i] = beta[i * CC + c] - mean[i * CC + c] * sc;
    }
    if (t == 0)
        g_bias[c] = sh[0] + sh[1] + sh[2] + sh[3] + sh[4] + sh[5] + sh[6];

    if (t < 169) {
        int ty = t / 13, tx = t % 13;
        int dy = ty - PAD, dx = tx - PAD;
        float acc = s[0] * lk_w[c * 169 + t];

        const float* ws[6]   = { w0, w1, w2, w3, w4, w5 };
        const int    KSa[6]  = { 5, 7, 7, 3, 3, 3 };
        const int    DILa[6] = { 1, 1, 2, 3, 4, 5 };
#pragma unroll
        for (int j = 0; j < 6; j++) {
            int r = DILa[j], k = KSa[j];
            if (dy % r == 0 && dx % r == 0) {
                int a  = dy / r + (k - 1) / 2;
                int b2 = dx / r + (k - 1) / 2;
                if (a >= 0 && a < k && b2 >= 0 && b2 < k)
                    acc += s[j + 1] * ws[j][c * k * k + a * k + b2];
            }
        }
        sweq[t] = acc;
    }
    __syncthreads();

    // Packed Toeplitz B: B[k][n] = Weq[k/20][k%20 - n] (valid taps only).
    for (int e = t; e < NKS * 32; e += blockDim.x) {
        int ks  = e >> 5;
        int r   = e & 31;
        int tig = r >> 3, g = r & 7;
        uint32_t bx = 0, by = 0;
#pragma unroll
        for (int half = 0; half < 2; half++) {
            int k = 8 * ks + tig + 4 * half;
            float v = 0.f;
            if (k < 260) {
                int ky  = k / 20;
                int c20 = k - ky * 20;
                int kx  = c20 - g;
                if (kx >= 0 && kx <= 12)
                    v = sweq[ky * 13 + kx];
            }
            if (half == 0) bx = f2tf32(v); else by = f2tf32(v);
        }
        g_B2[c * (NKS * 32) + e] = make_uint2(bx, by);
    }
}

// One ks-sweep computing m-tiles [MTLO, MTLO+MTCNT).
template<int MTLO, int MTCNT>
static __device__ __forceinline__ void gemm_pass(
    const uint32_t* __restrict__ sA, const uint2* __restrict__ sB,
    float* __restrict__ out, int ib0, int c, int xb, int g, int tig, float bb)
{
    int baseA[MTCNT], d8A[MTCNT];
#pragma unroll
    for (int i = 0; i < MTCNT; i++) {
        int m    = (MTLO + i) * 16 + g;
        int img  = (m >= HW) ? 1 : 0;
        int y    = m - HW * img;
        int m2   = m + 8;
        int img2 = (m2 >= HW) ? 1 : 0;
        int y2   = m2 - HW * img2;
        baseA[i] = img * TILE + y * TCOLS + xb * 8 + tig;
        d8A[i]   = (img2 * TILE + y2 * TCOLS) - (img * TILE + y * TCOLS);
    }

    float d[MTCNT][4];
#pragma unroll
    for (int i = 0; i < MTCNT; i++)
#pragma unroll
        for (int q = 0; q < 4; q++) d[i][q] = 0.f;

#pragma unroll
    for (int ks = 0; ks < NKS; ks++) {
        // Compile-time A offsets: 8ks%20 in {0,4,8,12,16}; +tig never wraps.
        const int kb   = 8 * ks;
        const int ky0  = kb / 20;
        const int c0   = kb - 20 * ky0;
        const int off0 = ky0 * TCOLS + c0;
        const int off1 = (c0 == 16) ? (ky0 + 1) * TCOLS : off0 + 4;

        uint2 bw = sB[ks * 32 + tig * 8 + g];

#pragma unroll
        for (int i = 0; i < MTCNT; i++) {
            int b0 = baseA[i], d8 = d8A[i];
            uint32_t a0 = sA[b0 + off0];
            uint32_t a1 = sA[b0 + d8 + off0];
            uint32_t a2 = sA[b0 + off1];
            uint32_t a3 = sA[b0 + d8 + off1];
            asm volatile(
                "mma.sync.aligned.m16n8k8.row.col.f32.tf32.tf32.f32 "
                "{%0,%1,%2,%3}, {%4,%5,%6,%7}, {%8,%9}, {%0,%1,%2,%3};"
                : "+f"(d[i][0]), "+f"(d[i][1]), "+f"(d[i][2]), "+f"(d[i][3])
                : "r"(a0), "r"(a1), "r"(a2), "r"(a3), "r"(bw.x), "r"(bw.y));
        }
    }

#pragma unroll
    for (int i = 0; i < MTCNT; i++) {
        int m    = (MTLO + i) * 16 + g;
        int img  = (m >= HW) ? 1 : 0;
        int y    = m - HW * img;
        int m2   = m + 8;
        int img2 = (m2 >= HW) ? 1 : 0;
        int y2   = m2 - HW * img2;
        float* o0 = out + (size_t)((ib0 + img)  * CC + c) * (HW * HW)
                        + y  * HW + xb * 8 + 2 * tig;
        float* o1 = out + (size_t)((ib0 + img2) * CC + c) * (HW * HW)
                        + y2 * HW + xb * 8 + 2 * tig;
        reinterpret_cast<float2*>(o0)[0] = make_float2(d[i][0] + bb, d[i][1] + bb);
        reinterpret_cast<float2*>(o1)[0] = make_float2(d[i][2] + bb, d[i][3] + bb);
    }
}

__global__ void __launch_bounds__(NTHR, 3) conv_tc(const float* __restrict__ x,
                                                   float* __restrict__ out)
{
    __shared__ uint32_t sA[2 * TILE];    // two padded 69x68 tiles, tf32 bits
    __shared__ uint2    sB[NKS * 32];    // 8448 B
    __shared__ float    sbias;

    int bid = blockIdx.x;
    int c   = bid & (CC - 1);
    int ib0 = (bid >> 8) * 2;
    int tid = threadIdx.x;

    const float* xim0 = x + (size_t)(ib0 * CC + c) * (HW * HW);
    const float* xim1 = xim0 + (size_t)CC * (HW * HW);

    for (int idx = tid; idx < 2 * TILE; idx += NTHR) {
        int e = idx, img = 0;
        if (e >= TILE) { img = 1; e -= TILE; }
        int r   = e / TCOLS;
        int cc2 = e - r * TCOLS;
        int iy = r - PAD, ix = cc2 - PAD;
        float v = 0.f;
        if ((unsigned)iy < (unsigned)HW && (unsigned)ix < (unsigned)HW)
            v = (img ? xim1 : xim0)[iy * HW + ix];
        sA[idx] = f2tf32(v);
    }
    for (int t = tid; t < NKS * 32; t += NTHR)
        sB[t] = g_B2[c * (NKS * 32) + t];
    if (tid == 0) sbias = g_bias[c];
    __syncthreads();

    int warp = tid >> 5;                 // xb
    int lane = tid & 31;
    int g    = lane >> 2;
    int tig  = lane & 3;

    float bb = sbias;

    gemm_pass<0, 4>(sA, sB, out, ib0, c, warp, g, tig, bb);   // m-tiles 0..3
    gemm_pass<4, 3>(sA, sB, out, ib0, c, warp, g, tig, bb);   // m-tiles 4..6
}

extern "C" void kernel_launch(void* const* d_in, const int* in_sizes, int n_in,
                              void* d_out, int out_size)
{
    const float* x    = (const float*)d_in[0];
    const float* lk_w = (const float*)d_in[1];
    const float* w0   = (const float*)d_in[2];
    const float* w1   = (const float*)d_in[3];
    const float* w2   = (const float*)d_in[4];
    const float* w3   = (const float*)d_in[5];
    const float* w4   = (const float*)d_in[6];
    const float* w5   = (const float*)d_in[7];
    const float* g    = (const float*)d_in[8];
    const float* b    = (const float*)d_in[9];
    const float* m    = (const float*)d_in[10];
    const float* v    = (const float*)d_in[11];
    float* out = (float*)d_out;

    prep_kernel<<<CC, 256>>>(lk_w, w0, w1, w2, w3, w4, w5, g, b, m, v);

    int nimg = out_size / (HW * HW * CC);   // 32
    int grid = (nimg / 2) * CC;             // 4096 CTAs
    conv_tc<<<grid, NTHR>>>(x, out);
}

// round 14
// speedup vs baseline: 1.7365x; 1.4732x over previous
#include <cuda_runtime.h>
#include <cstdint>

// DilatedReparamBlock == single 13x13 depthwise conv + per-channel bias.
//
// R13: back to R9's PROVEN mt-outer structure (198us, no DRAM bloom; every
// ks-outer variant bloomed 0.9GB parasitic DRAM traffic regardless of live
// accumulator count). Grafted improvements, both individually validated:
//   - compile-time A offsets (R10 math, bit-identical rel_err) replace the
//     runtime wrap trackers  -> inner step 11 -> 6 issue slots per MMA
//   - B packed as uint2 -> one conflict-free LDS64 per ks.

#define CC   256
#define HW   56
#define PAD  6
#define TROWS 69              // 68 padded rows + 1 zero row for K-padding
#define TCOLS 68
#define TILE (TROWS * TCOLS)  // 4692
#define NKS  33               // K = 264 = 33 * 8 (13*20=260 real + 4 zero)
#define NTHR 224              // 7 warps; warp w <-> output col block xb = w

__device__ uint2 g_B2[CC * NKS * 32];  // (tf32 B[8ks+tig][g], B[8ks+tig+4][g])
__device__ float g_bias[CC];

static __device__ __forceinline__ uint32_t f2tf32(float v)
{
    uint32_t u;
    asm("cvt.rna.tf32.f32 %0, %1;" : "=r"(u) : "f"(v));
    return u;
}

__global__ void prep_kernel(const float* __restrict__ lk_w,
                            const float* __restrict__ w0, const float* __restrict__ w1,
                            const float* __restrict__ w2, const float* __restrict__ w3,
                            const float* __restrict__ w4, const float* __restrict__ w5,
                            const float* __restrict__ gamma, const float* __restrict__ beta,
                            const float* __restrict__ mean,  const float* __restrict__ var)
{
    __shared__ float sweq[169];
    int c = blockIdx.x;
    int t = threadIdx.x;

    float s[7], sh[7];
#pragma unroll
    for (int i = 0; i < 7; i++) {
        float sc = gamma[i * CC + c] * rsqrtf(var[i * CC + c] + 1e-5f);
        s[i]  = sc;
        sh[i] = beta[i * CC + c] - mean[i * CC + c] * sc;
    }
    if (t == 0)
        g_bias[c] = sh[0] + sh[1] + sh[2] + sh[3] + sh[4] + sh[5] + sh[6];

    if (t < 169) {
        int ty = t / 13, tx = t % 13;
        int dy = ty - PAD, dx = tx - PAD;
        float acc = s[0] * lk_w[c * 169 + t];

        const float* ws[6]   = { w0, w1, w2, w3, w4, w5 };
        const int    KSa[6]  = { 5, 7, 7, 3, 3, 3 };
        const int    DILa[6] = { 1, 1, 2, 3, 4, 5 };
#pragma unroll
        for (int j = 0; j < 6; j++) {
            int r = DILa[j], k = KSa[j];
            if (dy % r == 0 && dx % r == 0) {
                int a  = dy / r + (k - 1) / 2;
                int b2 = dx / r + (k - 1) / 2;
                if (a >= 0 && a < k && b2 >= 0 && b2 < k)
                    acc += s[j + 1] * ws[j][c * k * k + a * k + b2];
            }
        }
        sweq[t] = acc;
    }
    __syncthreads();

    // Packed Toeplitz B: B[k][n] = Weq[k/20][k%20 - n] (valid taps only).
    for (int e = t; e < NKS * 32; e += blockDim.x) {
        int ks  = e >> 5;
        int r   = e & 31;
        int tig = r >> 3, g = r & 7;
        uint32_t bx = 0, by = 0;
#pragma unroll
        for (int half = 0; half < 2; half++) {
            int k = 8 * ks + tig + 4 * half;
            float v = 0.f;
            if (k < 260) {
                int ky  = k / 20;
                int c20 = k - ky * 20;
                int kx  = c20 - g;
                if (kx >= 0 && kx <= 12)
                    v = sweq[ky * 13 + kx];
            }
            if (half == 0) bx = f2tf32(v); else by = f2tf32(v);
        }
        g_B2[c * (NKS * 32) + e] = make_uint2(bx, by);
    }
}

__global__ void __launch_bounds__(NTHR, 4) conv_tc(const float* __restrict__ x,
                                                   float* __restrict__ out)
{
    __shared__ uint32_t sA[2 * TILE];    // two padded 69x68 tiles, tf32 bits
    __shared__ uint2    sB[NKS * 32];    // 8448 B
    __shared__ float    sbias;

    int bid = blockIdx.x;
    int c   = bid & (CC - 1);
    int ib0 = (bid >> 8) * 2;
    int tid = threadIdx.x;

    const float* xim0 = x + (size_t)(ib0 * CC + c) * (HW * HW);
    const float* xim1 = xim0 + (size_t)CC * (HW * HW);

    for (int idx = tid; idx < 2 * TILE; idx += NTHR) {
        int e = idx, img = 0;
        if (e >= TILE) { img = 1; e -= TILE; }
        int r   = e / TCOLS;
        int cc2 = e - r * TCOLS;
        int iy = r - PAD, ix = cc2 - PAD;
        float v = 0.f;
        if ((unsigned)iy < (unsigned)HW && (unsigned)ix < (unsigned)HW)
            v = (img ? xim1 : xim0)[iy * HW + ix];
        sA[idx] = f2tf32(v);
    }
    for (int t = tid; t < NKS * 32; t += NTHR)
        sB[t] = g_B2[c * (NKS * 32) + t];
    if (tid == 0) sbias = g_bias[c];
    __syncthreads();

    int warp = tid >> 5;                 // xb = warp (0..6)
    int lane = tid & 31;
    int g    = lane >> 2;                // groupID 0..7
    int tig  = lane & 3;                 // thread-in-group
    int xb   = warp;
    float bb = sbias;

    const uint2* sBw = sB + tig * 8 + g; // per-thread B base

#pragma unroll 1
    for (int mt = 0; mt < 7; mt++) {
        int m    = mt * 16 + g;
        int img  = (m >= HW) ? 1 : 0;
        int y    = m - HW * img;
        int m2   = m + 8;
        int img2 = (m2 >= HW) ? 1 : 0;
        int y2   = m2 - HW * img2;

        int base = img * TILE + y * TCOLS + xb * 8 + tig;
        int d8   = (img2 * TILE + y2 * TCOLS) - (img * TILE + y * TCOLS);

        float d0 = 0.f, d1 = 0.f, d2 = 0.f, d3 = 0.f;

#pragma unroll
        for (int ks = 0; ks < NKS; ks++) {
            // Compile-time A offsets: 8ks%20 in {0,4,8,12,16}; +tig<=3 never
            // wraps; the +4 operand wraps exactly when c0==16.
            const int kb   = 8 * ks;
            const int ky0  = kb / 20;
            const int c0   = kb - 20 * ky0;
            const int off0 = ky0 * TCOLS + c0;
            const int off1 = (c0 == 16) ? (ky0 + 1) * TCOLS : off0 + 4;

            uint2 bw = sBw[ks * 32];
            uint32_t a0 = sA[base + off0];
            uint32_t a1 = sA[base + d8 + off0];
            uint32_t a2 = sA[base + off1];
            uint32_t a3 = sA[base + d8 + off1];

            asm volatile(
                "mma.sync.aligned.m16n8k8.row.col.f32.tf32.tf32.f32 "
                "{%0,%1,%2,%3}, {%4,%5,%6,%7}, {%8,%9}, {%0,%1,%2,%3};"
                : "+f"(d0), "+f"(d1), "+f"(d2), "+f"(d3)
                : "r"(a0), "r"(a1), "r"(a2), "r"(a3), "r"(bw.x), "r"(bw.y));
        }

        float* o0 = out + (size_t)((ib0 + img)  * CC + c) * (HW * HW)
                        + y  * HW + xb * 8 + 2 * tig;
        float* o1 = out + (size_t)((ib0 + img2) * CC + c) * (HW * HW)
                        + y2 * HW + xb * 8 + 2 * tig;
        reinterpret_cast<float2*>(o0)[0] = make_float2(d0 + bb, d1 + bb);
        reinterpret_cast<float2*>(o1)[0] = make_float2(d2 + bb, d3 + bb);
    }
}

extern "C" void kernel_launch(void* const* d_in, const int* in_sizes, int n_in,
                              void* d_out, int out_size)
{
    const float* x    = (const float*)d_in[0];
    const float* lk_w = (const float*)d_in[1];
    const float* w0   = (const float*)d_in[2];
    const float* w1   = (const float*)d_in[3];
    const float* w2   = (const float*)d_in[4];
    const float* w3   = (const float*)d_in[5];
    const float* w4   = (const float*)d_in[6];
    const float* w5   = (const float*)d_in[7];
    const float* g    = (const float*)d_in[8];
    const float* b    = (const float*)d_in[9];
    const float* m    = (const float*)d_in[10];
    const float* v    = (const float*)d_in[11];
    float* out = (float*)d_out;

    prep_kernel<<<CC, 256>>>(lk_w, w0, w1, w2, w3, w4, w5, g, b, m, v);

    int nimg = out_size / (HW * HW * CC);   // 32
    int grid = (nimg / 2) * CC;             // 4096 CTAs
    conv_tc<<<grid, NTHR>>>(x, out);
}

// round 15
// speedup vs baseline: 1.9255x; 1.1089x over previous
#include <cuda_runtime.h>
#include <cstdint>

// DilatedReparamBlock == single 13x13 depthwise conv + per-channel bias.
//
// R14 = R13 (mt-outer tf32 Toeplitz GEMM, 234us, L1-wavefront-bound 92.7%)
// with the B fragments hoisted into registers ONCE per warp (33 x uint2,
// compile-time indexed). B was 33% of crossbar wavefronts (re-loaded for
// each of 7 m-tiles); now loaded once. Accumulator set stays at 4 -> the
// spill-bloom mode of R10-R12 shouldn't trigger (DRAM% adjudicates).

#define CC   256
#define HW   56
#define PAD  6
#define TROWS 69              // 68 padded rows + 1 zero row for K-padding
#define TCOLS 68
#define TILE (TROWS * TCOLS)  // 4692
#define NKS  33               // K = 264 = 33 * 8 (13*20=260 real + 4 zero)
#define NTHR 224              // 7 warps; warp w <-> output col block xb = w

__device__ uint2 g_B2[CC * NKS * 32];  // (tf32 B[8ks+tig][g], B[8ks+tig+4][g])
__device__ float g_bias[CC];

static __device__ __forceinline__ uint32_t f2tf32(float v)
{
    uint32_t u;
    asm("cvt.rna.tf32.f32 %0, %1;" : "=r"(u) : "f"(v));
    return u;
}

__global__ void prep_kernel(const float* __restrict__ lk_w,
                            const float* __restrict__ w0, const float* __restrict__ w1,
                            const float* __restrict__ w2, const float* __restrict__ w3,
                            const float* __restrict__ w4, const float* __restrict__ w5,
                            const float* __restrict__ gamma, const float* __restrict__ beta,
                            const float* __restrict__ mean,  const float* __restrict__ var)
{
    __shared__ float sweq[169];
    int c = blockIdx.x;
    int t = threadIdx.x;

    float s[7], sh[7];
#pragma unroll
    for (int i = 0; i < 7; i++) {
        float sc = gamma[i * CC + c] * rsqrtf(var[i * CC + c] + 1e-5f);
        s[i]  = sc;
        sh[i] = beta[i * CC + c] - mean[i * CC + c] * sc;
    }
    if (t == 0)
        g_bias[c] = sh[0] + sh[1] + sh[2] + sh[3] + sh[4] + sh[5] + sh[6];

    if (t < 169) {
        int ty = t / 13, tx = t % 13;
        int dy = ty - PAD, dx = tx - PAD;
        float acc = s[0] * lk_w[c * 169 + t];

        const float* ws[6]   = { w0, w1, w2, w3, w4, w5 };
        const int    KSa[6]  = { 5, 7, 7, 3, 3, 3 };
        const int    DILa[6] = { 1, 1, 2, 3, 4, 5 };
#pragma unroll
        for (int j = 0; j < 6; j++) {
            int r = DILa[j], k = KSa[j];
            if (dy % r == 0 && dx % r == 0) {
                int a  = dy / r + (k - 1) / 2;
                int b2 = dx / r + (k - 1) / 2;
                if (a >= 0 && a < k && b2 >= 0 && b2 < k)
                    acc += s[j + 1] * ws[j][c * k * k + a * k + b2];
            }
        }
        sweq[t] = acc;
    }
    __syncthreads();

    // Packed Toeplitz B: B[k][n] = Weq[k/20][k%20 - n] (valid taps only).
    for (int e = t; e < NKS * 32; e += blockDim.x) {
        int ks  = e >> 5;
        int r   = e & 31;
        int tig = r >> 3, g = r & 7;
        uint32_t bx = 0, by = 0;
#pragma unroll
        for (int half = 0; half < 2; half++) {
            int k = 8 * ks + tig + 4 * half;
            float v = 0.f;
            if (k < 260) {
                int ky  = k / 20;
                int c20 = k - ky * 20;
                int kx  = c20 - g;
                if (kx >= 0 && kx <= 12)
                    v = sweq[ky * 13 + kx];
            }
            if (half == 0) bx = f2tf32(v); else by = f2tf32(v);
        }
        g_B2[c * (NKS * 32) + e] = make_uint2(bx, by);
    }
}

__global__ void __launch_bounds__(NTHR, 3) conv_tc(const float* __restrict__ x,
                                                   float* __restrict__ out)
{
    __shared__ uint32_t sA[2 * TILE];    // two padded 69x68 tiles, tf32 bits
    __shared__ uint2    sB[NKS * 32];    // 8448 B
    __shared__ float    sbias;

    int bid = blockIdx.x;
    int c   = bid & (CC - 1);
    int ib0 = (bid >> 8) * 2;
    int tid = threadIdx.x;

    const float* xim0 = x + (size_t)(ib0 * CC + c) * (HW * HW);
    const float* xim1 = xim0 + (size_t)CC * (HW * HW);

    for (int idx = tid; idx < 2 * TILE; idx += NTHR) {
        int e = idx, img = 0;
        if (e >= TILE) { img = 1; e -= TILE; }
        int r   = e / TCOLS;
        int cc2 = e - r * TCOLS;
        int iy = r - PAD, ix = cc2 - PAD;
        float v = 0.f;
        if ((unsigned)iy < (unsigned)HW && (unsigned)ix < (unsigned)HW)
            v = (img ? xim1 : xim0)[iy * HW + ix];
        sA[idx] = f2tf32(v);
    }
    for (int t = tid; t < NKS * 32; t += NTHR)
        sB[t] = g_B2[c * (NKS * 32) + t];
    if (tid == 0) sbias = g_bias[c];
    __syncthreads();

    int warp = tid >> 5;                 // xb = warp (0..6)
    int lane = tid & 31;
    int g    = lane >> 2;                // groupID 0..7
    int tig  = lane & 3;                 // thread-in-group
    int xb   = warp;
    float bb = sbias;

    // Hoist all B fragments into registers: statically indexed, read-only.
    uint2 breg[NKS];
    {
        const uint2* sBw = sB + tig * 8 + g;
#pragma unroll
        for (int ks = 0; ks < NKS; ks++) breg[ks] = sBw[ks * 32];
    }

#pragma unroll 1
    for (int mt = 0; mt < 7; mt++) {
        int m    = mt * 16 + g;
        int img  = (m >= HW) ? 1 : 0;
        int y    = m - HW * img;
        int m2   = m + 8;
        int img2 = (m2 >= HW) ? 1 : 0;
        int y2   = m2 - HW * img2;

        int base = img * TILE + y * TCOLS + xb * 8 + tig;
        int d8   = (img2 * TILE + y2 * TCOLS) - (img * TILE + y * TCOLS);

        float d0 = 0.f, d1 = 0.f, d2 = 0.f, d3 = 0.f;

#pragma unroll
        for (int ks = 0; ks < NKS; ks++) {
            // Compile-time A offsets: 8ks%20 in {0,4,8,12,16}; +tig<=3 never
            // wraps; the +4 operand wraps to the next row when c0==16.
            const int kb   = 8 * ks;
            const int ky0  = kb / 20;
            const int c0   = kb - 20 * ky0;
            const int off0 = ky0 * TCOLS + c0;
            const int off1 = (c0 == 16) ? (ky0 + 1) * TCOLS : off0 + 4;

            uint32_t a0 = sA[base + off0];
            uint32_t a1 = sA[base + d8 + off0];
            uint32_t a2 = sA[base + off1];
            uint32_t a3 = sA[base + d8 + off1];

            asm volatile(
                "mma.sync.aligned.m16n8k8.row.col.f32.tf32.tf32.f32 "
                "{%0,%1,%2,%3}, {%4,%5,%6,%7}, {%8,%9}, {%0,%1,%2,%3};"
                : "+f"(d0), "+f"(d1), "+f"(d2), "+f"(d3)
                : "r"(a0), "r"(a1), "r"(a2), "r"(a3),
                  "r"(breg[ks].x), "r"(breg[ks].y));
        }

        float* o0 = out + (size_t)((ib0 + img)  * CC + c) * (HW * HW)
                        + y  * HW + xb * 8 + 2 * tig;
        float* o1 = out + (size_t)((ib0 + img2) * CC + c) * (HW * HW)
                        + y2 * HW + xb * 8 + 2 * tig;
        reinterpret_cast<float2*>(o0)[0] = make_float2(d0 + bb, d1 + bb);
        reinterpret_cast<float2*>(o1)[0] = make_float2(d2 + bb, d3 + bb);
    }
}

extern "C" void kernel_launch(void* const* d_in, const int* in_sizes, int n_in,
                              void* d_out, int out_size)
{
    const float* x    = (const float*)d_in[0];
    const float* lk_w = (const float*)d_in[1];
    const float* w0   = (const float*)d_in[2];
    const float* w1   = (const float*)d_in[3];
    const float* w2   = (const float*)d_in[4];
    const float* w3   = (const float*)d_in[5];
    const float* w4   = (const float*)d_in[6];
    const float* w5   = (const float*)d_in[7];
    const float* g    = (const float*)d_in[8];
    const float* b    = (const float*)d_in[9];
    const float* m    = (const float*)d_in[10];
    const float* v    = (const float*)d_in[11];
    float* out = (float*)d_out;

    prep_kernel<<<CC, 256>>>(lk_w, w0, w1, w2, w3, w4, w5, g, b, m, v);

    int nimg = out_size / (HW * HW * CC);   // 32
    int grid = (nimg / 2) * CC;             // 4096 CTAs
    conv_tc<<<grid, NTHR>>>(x, out);
}